// round 9
// baseline (speedup 1.0000x reference)
#include <cuda_runtime.h>

#define CHUNK  256
#define MAXW   40
#define MAXN   (MAXW * CHUNK)   // 10240
#define MAXP   1000
#define SB     4096
#define KCAP   1536

typedef unsigned long long u64;

// ---- static device scratch (no allocations allowed) ----
__device__ ulonglong4 g_maskT[(size_t)MAXW * MAXN];  // [word][row] suppression bits
__device__ ulonglong4 g_diag[MAXN];                  // diagonal-block masks
__device__ float4     g_sboxes[MAXN];                // boxes in sorted order
__device__ float      g_sscores[MAXN];               // scores in sorted order
__device__ ulonglong4 g_keep[MAXW];                  // keep bits per 256-chunk
__device__ int        g_prefix[MAXW];                // kept-count prefix per chunk
__device__ int        g_base[SB];                    // bucket base (descending order)
__device__ int        g_members[MAXN];               // indices grouped by bucket

__device__ __forceinline__ int bucket_of(float s) {
    int b = (int)(s * 4096.0f);           // monotone for s >= 0
    return max(0, min(SB - 1, b));
}

// ---------------------------------------------------------------------------
// S1: fused single-block sort front-end: histogram + descending exclusive
// scan + bucket fill. All bucket state in shared (no cross-replay cleanup).
// ---------------------------------------------------------------------------
__global__ void k_sortA(const float* __restrict__ scores, int N) {
    __shared__ int s_cnt[SB];
    __shared__ int s_base[SB];
    __shared__ int wsum[32];
    int tid = threadIdx.x, lane = tid & 31, wid = tid >> 5;

    for (int b = tid; b < SB; b += 1024) s_cnt[b] = 0;
    __syncthreads();
    for (int i = tid; i < N; i += 1024)
        atomicAdd(&s_cnt[bucket_of(scores[i])], 1);
    __syncthreads();

    int cbase = 0;
    for (int k = 0; k < SB / 1024; k++) {
        int b = SB - 1 - (k * 1024 + tid);   // descending bucket order
        int v = s_cnt[b];
        int x = v;
        #pragma unroll
        for (int o = 1; o < 32; o <<= 1) {
            int y = __shfl_up_sync(~0u, x, o);
            if (lane >= o) x += y;
        }
        if (lane == 31) wsum[wid] = x;
        __syncthreads();
        if (wid == 0) {
            int s = wsum[lane];
            #pragma unroll
            for (int o = 1; o < 32; o <<= 1) {
                int y = __shfl_up_sync(~0u, s, o);
                if (lane >= o) s += y;
            }
            wsum[lane] = s;
        }
        __syncthreads();
        s_base[b] = cbase + (x - v) + (wid ? wsum[wid - 1] : 0);
        cbase += wsum[31];
        __syncthreads();
    }

    for (int b = tid; b < SB; b += 1024) { s_cnt[b] = 0; g_base[b] = s_base[b]; }
    __syncthreads();
    for (int i = tid; i < N; i += 1024) {
        int b = bucket_of(scores[i]);
        int slot = s_base[b] + atomicAdd(&s_cnt[b], 1);
        g_members[slot] = i;
    }
}

// ---------------------------------------------------------------------------
// S2: exact stable rank within bucket + scatter (grid-parallel).
// ---------------------------------------------------------------------------
__global__ void k_place(const float4* __restrict__ boxes,
                        const float* __restrict__ scores, int N) {
    int i = blockIdx.x * blockDim.x + threadIdx.x;
    if (i >= N) return;
    float si = scores[i];
    int b = bucket_of(si);
    int base = g_base[b];
    int cb   = ((b > 0) ? g_base[b - 1] : N) - base;
    int r = base;
    for (int t = 0; t < cb; t++) {
        int j = g_members[base + t];
        if (j == i) continue;
        float sj = scores[j];
        r += (sj > si) || (sj == si && j < i);
    }
    g_sboxes[r]  = boxes[i];
    g_sscores[r] = si;
}

// ---------------------------------------------------------------------------
// K2: pairwise IoU suppression bitmask, 256x256 tiles, upper triangle.
// suppress <=> IoU > 0.5 <=> 3*inter > areaR + areaC  (division-free).
// Padding boxes all-zero -> never suppress. Stores TRANSPOSED g_maskT[word][row].
// ---------------------------------------------------------------------------
__global__ void k_mask(int N, int W) {
    int cb = blockIdx.x, rb = blockIdx.y;
    if (cb < rb) return;
    __shared__ float4 cbox[CHUNK];
    __shared__ float  carea[CHUNK];
    int t  = threadIdx.x;
    int cg = cb * CHUNK + t;
    float4 cv = (cg < N) ? g_sboxes[cg] : make_float4(0.f, 0.f, 0.f, 0.f);
    cbox[t]  = cv;
    carea[t] = (cv.z - cv.x) * (cv.w - cv.y);
    __syncthreads();

    int rg = rb * CHUNK + t;
    if (rg >= N) return;
    float4 r = g_sboxes[rg];
    float ra = (r.z - r.x) * (r.w - r.y);

    u64 m[4] = {0ull, 0ull, 0ull, 0ull};
    if (cb > rb) {
        #pragma unroll
        for (int q = 0; q < 4; q++) {
            u64 mm = 0ull;
            #pragma unroll 32
            for (int jj = 0; jj < 64; jj++) {
                int j = q * 64 + jj;
                float4 c = cbox[j];
                float ix1 = fmaxf(r.x, c.x), iy1 = fmaxf(r.y, c.y);
                float ix2 = fminf(r.z, c.z), iy2 = fminf(r.w, c.w);
                float inter = fmaxf(ix2 - ix1, 0.0f) * fmaxf(iy2 - iy1, 0.0f);
                if (3.0f * inter > ra + carea[j]) mm |= 1ull << jj;
            }
            m[q] = mm;
        }
    } else {
        // diagonal tile: only suppress later (lower-score) boxes j > t
        #pragma unroll 4
        for (int j = 0; j < CHUNK; j++) {
            if (j <= t) continue;
            float4 c = cbox[j];
            float ix1 = fmaxf(r.x, c.x), iy1 = fmaxf(r.y, c.y);
            float ix2 = fminf(r.z, c.z), iy2 = fminf(r.w, c.w);
            float inter = fmaxf(ix2 - ix1, 0.0f) * fmaxf(iy2 - iy1, 0.0f);
            if (3.0f * inter > ra + carea[j]) m[j >> 6] |= 1ull << (j & 63);
        }
        g_diag[rg] = make_ulonglong4(m[0], m[1], m[2], m[3]);
    }
    g_maskT[(size_t)cb * MAXN + rg] = make_ulonglong4(m[0], m[1], m[2], m[3]);
}

__device__ __forceinline__ int ffs256_4(u64 p0, u64 p1, u64 p2, u64 p3) {
    if (p0) return __ffsll((long long)p0) - 1;
    if (p1) return 63 + __ffsll((long long)p1);
    if (p2) return 127 + __ffsll((long long)p2);
    if (p3) return 191 + __ffsll((long long)p3);
    return -1;
}

__device__ __forceinline__ u64 vmask64(int valid) {
    return (valid >= 64) ? ~0ull : ((valid <= 0) ? 0ull : ((1ull << valid) - 1ull));
}

// ---------------------------------------------------------------------------
// phase A: serial greedy within one 256-chunk with speculative diag prefetch.
// Appends kept rows (global ids) to klist, returns count.
// ---------------------------------------------------------------------------
__device__ __forceinline__ int phaseA(const ulonglong4* d,
                                      u64 r0, u64 r1, u64 r2, u64 r3,
                                      int valid, int gbase,
                                      int* klist, ulonglong4& keep) {
    u64 p0 = ~r0 & vmask64(valid);
    u64 p1 = ~r1 & vmask64(valid - 64);
    u64 p2 = ~r2 & vmask64(valid - 128);
    u64 p3 = ~r3 & vmask64(valid - 192);
    u64 k0 = 0, k1 = 0, k2 = 0, k3 = 0;
    int n = 0;
    int i = ffs256_4(p0, p1, p2, p3);
    ulonglong4 dd = (i >= 0) ? d[i] : make_ulonglong4(0, 0, 0, 0);
    while (i >= 0) {
        u64 bit = 1ull << (i & 63);
        if (i < 64)       { k0 |= bit; p0 &= ~bit; }
        else if (i < 128) { k1 |= bit; p1 &= ~bit; }
        else if (i < 192) { k2 |= bit; p2 &= ~bit; }
        else              { k3 |= bit; p3 &= ~bit; }
        klist[n++] = gbase + i;
        int j = ffs256_4(p0, p1, p2, p3);              // speculative candidate
        ulonglong4 ddj = (j >= 0) ? d[j] : make_ulonglong4(0, 0, 0, 0);
        p0 &= ~dd.x; p1 &= ~dd.y; p2 &= ~dd.z; p3 &= ~dd.w;
        int i2 = ffs256_4(p0, p1, p2, p3);
        if (i2 == j) { i = j; dd = ddj; }
        else { i = i2; if (i2 >= 0) dd = d[i2]; }
    }
    keep = make_ulonglong4(k0, k1, k2, k3);
    return n;
}

// ---------------------------------------------------------------------------
// K3: lazy greedy scan over 256-wide chunks.
//   phase 1: ALL 256 threads gather OR over the global kept list of
//            maskT[wc][kept_row] (independent 32B loads, 8 warps).
//   phase 2: thread 0 reduces partials + runs phase A; threads 128..255
//            prefetch diag tile wc+1 concurrently.
// Early termination once total kept >= MAXP.
// ---------------------------------------------------------------------------
__global__ void k_scan(int N, int W) {
    __shared__ ulonglong4 diagbuf[2][CHUNK];
    __shared__ ulonglong4 s_part[8];
    __shared__ int s_klist[KCAP];
    __shared__ int s_K, s_stop, s_cstop, s_total;
    int tid = threadIdx.x, lane = tid & 31, wid = tid >> 5;

    diagbuf[0][tid] = (tid < N) ? g_diag[tid] : make_ulonglong4(0, 0, 0, 0);
    {
        int g = CHUNK + tid;
        diagbuf[1][tid] = (W > 1 && g < N) ? g_diag[g] : make_ulonglong4(0, 0, 0, 0);
    }
    if (tid == 0) { s_stop = 0; s_cstop = W; s_total = 0; s_K = 0; }
    __syncthreads();

    // chunk 0
    if (tid == 0) {
        ulonglong4 kp;
        int n = phaseA(diagbuf[0], 0, 0, 0, 0, min(N, CHUNK), 0, s_klist, kp);
        g_keep[0] = kp;
        g_prefix[0] = 0;
        int tot = __popcll(kp.x) + __popcll(kp.y) + __popcll(kp.z) + __popcll(kp.w);
        s_total = tot; s_K = n;
        if (tot >= MAXP) { s_stop = 1; s_cstop = 1; }
    }
    __syncthreads();

    for (int c = 0; c + 1 < W; c++) {
        if (s_stop) break;
        int wc = c + 1;
        int K = s_K;

        // phase 1: cooperative gather of chunk wc's suppression word
        const ulonglong4* mp = g_maskT + (size_t)wc * MAXN;
        u64 a0 = 0, a1 = 0, a2 = 0, a3 = 0;
        for (int t = tid; t < K; t += 256) {
            ulonglong4 v = mp[s_klist[t]];
            a0 |= v.x; a1 |= v.y; a2 |= v.z; a3 |= v.w;
        }
        #pragma unroll
        for (int o = 16; o; o >>= 1) {
            a0 |= __shfl_xor_sync(~0u, a0, o);
            a1 |= __shfl_xor_sync(~0u, a1, o);
            a2 |= __shfl_xor_sync(~0u, a2, o);
            a3 |= __shfl_xor_sync(~0u, a3, o);
        }
        if (lane == 0) s_part[wid] = make_ulonglong4(a0, a1, a2, a3);
        __syncthreads();

        // phase 2: thread 0 reduce + phase A; tid>=128 prefetch diag wc+1
        if (tid == 0) {
            u64 r0 = 0, r1 = 0, r2 = 0, r3 = 0;
            #pragma unroll
            for (int p = 0; p < 8; p++) {
                ulonglong4 v = s_part[p];
                r0 |= v.x; r1 |= v.y; r2 |= v.z; r3 |= v.w;
            }
            ulonglong4 kp;
            int n = phaseA(diagbuf[wc & 1], r0, r1, r2, r3, N - wc * CHUNK,
                           wc * CHUNK, s_klist + K, kp);
            g_keep[wc] = kp;
            g_prefix[wc] = s_total;
            int tot = s_total + __popcll(kp.x) + __popcll(kp.y)
                              + __popcll(kp.z) + __popcll(kp.w);
            s_total = tot; s_K = K + n;
            if (tot >= MAXP) { s_stop = 1; s_cstop = wc + 1; }
        } else if (tid >= 128 && c + 2 < W) {
            int g0 = (c + 2) * CHUNK + (tid - 128);
            int g1 = g0 + 128;
            diagbuf[c & 1][tid - 128] =
                (g0 < N) ? g_diag[g0] : make_ulonglong4(0, 0, 0, 0);
            diagbuf[c & 1][tid] =
                (g1 < N) ? g_diag[g1] : make_ulonglong4(0, 0, 0, 0);
        }
        __syncthreads();
    }

    int cstop = s_cstop;
    for (int c2 = cstop + tid; c2 < W; c2 += 256)
        g_keep[c2] = make_ulonglong4(0, 0, 0, 0);
}

// ---------------------------------------------------------------------------
// K4: apply MAX_PROPOSALS cutoff and emit outputs:
//   out[0 : 4N) boxes | out[4N : 5N) scores | out[5N : 6N) keep as 0/1
// ---------------------------------------------------------------------------
__global__ void k_out(float* __restrict__ out, int N) {
    int p = blockIdx.x * blockDim.x + threadIdx.x;
    if (p >= N) return;
    int c = p >> 8, i = p & 255;
    ulonglong4 kw = g_keep[c];
    u64 w[4] = {kw.x, kw.y, kw.z, kw.w};
    int wi = i >> 6, ii = i & 63;
    bool kept = (w[wi] >> ii) & 1ull;
    int below = 0;
    #pragma unroll
    for (int q = 0; q < 4; q++) {
        u64 mask = (q < wi) ? ~0ull : ((q == wi) ? ((1ull << ii) - 1ull) : 0ull);
        below += __popcll(w[q] & mask);
    }
    int r = g_prefix[c] + below;
    bool fin = kept && (r < MAXP);

    float4 b = fin ? g_sboxes[p] : make_float4(0.f, 0.f, 0.f, 0.f);
    ((float4*)out)[p] = b;
    out[4 * N + p] = fin ? g_sscores[p] : 0.0f;
    out[5 * N + p] = fin ? 1.0f : 0.0f;
}

// ---------------------------------------------------------------------------
extern "C" void kernel_launch(void* const* d_in, const int* in_sizes, int n_in,
                              void* d_out, int out_size) {
    const float4* boxes  = (const float4*)d_in[0];
    const float*  scores = (const float*)d_in[1];
    int N = in_sizes[1];
    int W = (N + CHUNK - 1) / CHUNK;

    k_sortA<<<1, 1024>>>(scores, N);
    k_place<<<(N + 255) / 256, 256>>>(boxes, scores, N);

    dim3 g2(W, W);
    k_mask<<<g2, CHUNK>>>(N, W);

    k_scan<<<1, 256>>>(N, W);

    k_out<<<(N + 255) / 256, 256>>>((float*)d_out, N);
}